// round 2
// baseline (speedup 1.0000x reference)
#include <cuda_runtime.h>
#include <cuda_bf16.h>
#include <cstdint>

// Problem constants (fixed by the dataset)
constexpr int NTOK = 16384;
constexpr int INF  = 512;
constexpr int OUTF = 512;
constexpr int NT   = 16;

// GEMM tiling
constexpr int BM = 128;
constexpr int BN = 128;
constexpr int BK = 16;
constexpr int THREADS = 256;
constexpr int KTILES = INF / BK;          // 32
constexpr int MAX_MTILES = NTOK / BM;     // 128 (worst case: all tokens one type)

// ---------------------------------------------------------------------------
// Scratch (no allocations allowed -> __device__ globals)
// ---------------------------------------------------------------------------
__device__ int g_count[NT];
__device__ int g_offset[NT];
__device__ int g_fill[NT];
__device__ int g_is64;         // 1 if i_type is int64, 0 if int32
__device__ int g_perm[NTOK];   // token ids grouped by type

// Read type i from the raw i_type buffer under either dtype interpretation.
__device__ __forceinline__ int get_type(const int* __restrict__ w, int i) {
    int v = g_is64 ? w[2 * i] : w[i];
    return v & (NT - 1);       // crash-proofing; no-op for valid types
}

// ---------------------------------------------------------------------------
// 1) init: zero counters + detect i_type dtype.
//    If int64 (LE), words at odd indices are high halves == 0 for all 8192
//    pairs we test. If int32, those words are real types (mostly nonzero).
//    All reads lie in [0, 16384) int32s — in-bounds for both interpretations.
// ---------------------------------------------------------------------------
__global__ void init_kernel(const int* __restrict__ w) {
    __shared__ int sOr[256];
    int tid = threadIdx.x;
    int acc = 0;
    for (int i = tid; i < NTOK / 2; i += 256) acc |= w[2 * i + 1];
    sOr[tid] = acc;
    __syncthreads();
    for (int s = 128; s > 0; s >>= 1) {
        if (tid < s) sOr[tid] |= sOr[tid + s];
        __syncthreads();
    }
    if (tid == 0) g_is64 = (sOr[0] == 0) ? 1 : 0;
    if (tid < NT) {
        g_count[tid] = 0;
        g_fill[tid]  = 0;
    }
}

// ---------------------------------------------------------------------------
// 2) histogram of types (smem-aggregated)
// ---------------------------------------------------------------------------
__global__ void hist_kernel(const int* __restrict__ w) {
    __shared__ int h[NT];
    int tid = threadIdx.x;
    if (tid < NT) h[tid] = 0;
    __syncthreads();
    int i = blockIdx.x * blockDim.x + tid;
    if (i < NTOK) {
        atomicAdd(&h[get_type(w, i)], 1);
    }
    __syncthreads();
    if (tid < NT && h[tid] > 0) atomicAdd(&g_count[tid], h[tid]);
}

// ---------------------------------------------------------------------------
// 3) exclusive scan over 16 counts
// ---------------------------------------------------------------------------
__global__ void scan_kernel() {
    int s = 0;
    for (int t = 0; t < NT; t++) {
        g_offset[t] = s;
        s += g_count[t];
    }
}

// ---------------------------------------------------------------------------
// 4) scatter token ids into grouped order (block-aggregated atomics)
// ---------------------------------------------------------------------------
__global__ void scatter_kernel(const int* __restrict__ w) {
    __shared__ int h[NT];
    __shared__ int base[NT];
    int tid = threadIdx.x;
    if (tid < NT) h[tid] = 0;
    __syncthreads();

    int i = blockIdx.x * blockDim.x + tid;
    int t = 0, local = 0;
    if (i < NTOK) {
        t = get_type(w, i);
        local = atomicAdd(&h[t], 1);
    }
    __syncthreads();
    if (tid < NT) {
        base[tid] = (h[tid] > 0) ? atomicAdd(&g_fill[tid], h[tid]) : 0;
    }
    __syncthreads();
    if (i < NTOK) {
        g_perm[g_offset[t] + base[t] + local] = i;
    }
}

// ---------------------------------------------------------------------------
// 5) grouped GEMM with gather/scatter rows
//    C[m, n] = sum_k A[idx[m], k] * W[t][n, k] + bias[t][n]
//    Both A and W are K-contiguous (row-major over k) -> NT layout.
// ---------------------------------------------------------------------------
__global__ void __launch_bounds__(THREADS, 2)
gemm_kernel(const float* __restrict__ input,
            const float* __restrict__ weight,
            const float* __restrict__ bias,
            float* __restrict__ out) {
    const int t   = blockIdx.z;
    const int cnt = g_count[t];
    const int m0  = blockIdx.y * BM;
    if (m0 >= cnt) return;                    // early-exit empty tiles
    const int off = g_offset[t];
    const int n0  = blockIdx.x * BN;

    __shared__ __align__(16) float As[2][BK][BM + 4];
    __shared__ __align__(16) float Bs[2][BK][BN + 4];
    __shared__ int s_idx[BM];

    const int tid = threadIdx.x;
    const int tx  = tid & 15;                 // n direction
    const int ty  = tid >> 4;                 // m direction

    // load gathered row indices for this tile
    if (tid < BM) {
        int m = m0 + tid;
        s_idx[tid] = (m < cnt) ? g_perm[off + m] : -1;
    }
    __syncthreads();

    const float* wt = weight + (size_t)t * OUTF * INF;

    // each thread loads 2 float4 of A and 2 float4 of B per k-tile.
    // l in [0,512): k4 = l >> 7 (0..3 -> k = 4*k4), m = l & 127.
    // warp => k4 fixed, m consecutive => STS bank = (4k + m) % 32 conflict-free.
    float4 pa[2], pb[2];

    auto load_global = [&](int k0) {
#pragma unroll
        for (int i = 0; i < 2; i++) {
            int l  = tid + THREADS * i;
            int k4 = l >> 7;
            int m  = l & 127;
            int r  = s_idx[m];
            if (r >= 0) {
                pa[i] = *(const float4*)&input[(size_t)r * INF + k0 + k4 * 4];
            } else {
                pa[i] = make_float4(0.f, 0.f, 0.f, 0.f);
            }
            int n = n0 + m;
            pb[i] = *(const float4*)&wt[(size_t)n * INF + k0 + k4 * 4];
        }
    };

    auto store_smem = [&](int buf) {
#pragma unroll
        for (int i = 0; i < 2; i++) {
            int l  = tid + THREADS * i;
            int k4 = l >> 7;
            int m  = l & 127;
            As[buf][k4 * 4 + 0][m] = pa[i].x;
            As[buf][k4 * 4 + 1][m] = pa[i].y;
            As[buf][k4 * 4 + 2][m] = pa[i].z;
            As[buf][k4 * 4 + 3][m] = pa[i].w;
            Bs[buf][k4 * 4 + 0][m] = pb[i].x;
            Bs[buf][k4 * 4 + 1][m] = pb[i].y;
            Bs[buf][k4 * 4 + 2][m] = pb[i].z;
            Bs[buf][k4 * 4 + 3][m] = pb[i].w;
        }
    };

    float c[8][8];
#pragma unroll
    for (int i = 0; i < 8; i++)
#pragma unroll
        for (int j = 0; j < 8; j++) c[i][j] = 0.f;

    // prologue: tile 0
    load_global(0);
    store_smem(0);
    __syncthreads();

    for (int kt = 0; kt < KTILES; kt++) {
        const int cur = kt & 1;
        if (kt + 1 < KTILES) {
            load_global((kt + 1) * BK);       // LDG overlaps compute below
        }

#pragma unroll
        for (int k = 0; k < BK; k++) {
            float4 a0 = *(const float4*)&As[cur][k][ty * 4];
            float4 a1 = *(const float4*)&As[cur][k][64 + ty * 4];
            float4 b0 = *(const float4*)&Bs[cur][k][tx * 4];
            float4 b1 = *(const float4*)&Bs[cur][k][64 + tx * 4];
            float av[8] = {a0.x, a0.y, a0.z, a0.w, a1.x, a1.y, a1.z, a1.w};
            float bv[8] = {b0.x, b0.y, b0.z, b0.w, b1.x, b1.y, b1.z, b1.w};
#pragma unroll
            for (int i = 0; i < 8; i++)
#pragma unroll
                for (int j = 0; j < 8; j++) c[i][j] = fmaf(av[i], bv[j], c[i][j]);
        }

        if (kt + 1 < KTILES) {
            store_smem(cur ^ 1);
        }
        __syncthreads();
    }

    // epilogue: bias + scatter store
    float4 bias0 = *(const float4*)&bias[t * OUTF + n0 + tx * 4];
    float4 bias1 = *(const float4*)&bias[t * OUTF + n0 + 64 + tx * 4];

#pragma unroll
    for (int i = 0; i < 8; i++) {
        int mrow = (i < 4) ? (ty * 4 + i) : (64 + ty * 4 + (i - 4));
        int r = s_idx[mrow];
        if (r < 0) continue;
        float4 o0 = make_float4(c[i][0] + bias0.x, c[i][1] + bias0.y,
                                c[i][2] + bias0.z, c[i][3] + bias0.w);
        float4 o1 = make_float4(c[i][4] + bias1.x, c[i][5] + bias1.y,
                                c[i][6] + bias1.z, c[i][7] + bias1.w);
        *(float4*)&out[(size_t)r * OUTF + n0 + tx * 4]      = o0;
        *(float4*)&out[(size_t)r * OUTF + n0 + 64 + tx * 4] = o1;
    }
}

// ---------------------------------------------------------------------------
// launch
// ---------------------------------------------------------------------------
extern "C" void kernel_launch(void* const* d_in, const int* in_sizes, int n_in,
                              void* d_out, int out_size) {
    const float* input  = (const float*)d_in[0];
    const int*   itype  = (const int*)d_in[1];   // dtype resolved on device
    const float* weight = (const float*)d_in[2];
    const float* bias   = (const float*)d_in[3];
    float*       out    = (float*)d_out;

    init_kernel<<<1, 256>>>(itype);
    hist_kernel<<<NTOK / 256, 256>>>(itype);
    scan_kernel<<<1, 1>>>();
    scatter_kernel<<<NTOK / 256, 256>>>(itype);

    dim3 grid(OUTF / BN, MAX_MTILES, NT);
    gemm_kernel<<<grid, THREADS>>>(input, weight, bias, out);
}

// round 6
// speedup vs baseline: 2.1774x; 2.1774x over previous
#include <cuda_runtime.h>
#include <cuda_bf16.h>
#include <cstdint>

// ---------------------------------------------------------------------------
// Problem constants
// ---------------------------------------------------------------------------
constexpr int NTOK = 16384;
constexpr int INF  = 512;
constexpr int OUTF = 512;
constexpr int NT   = 16;

constexpr int BM = 128;
constexpr int BN = 128;
constexpr int CHUNK  = 32;             // K fp32 elements per pipeline chunk
constexpr int NCHUNK = INF / CHUNK;    // 16
constexpr int THREADS = 256;
constexpr int MAX_MTILES = NTOK / BM;  // 128

// Dynamic smem layout (bytes)
constexpr int SM_IDX     = 0;                      // 128 * 4
constexpr int SM_BIAS    = 512;                    // 128 * 4
constexpr int SM_STAGE   = 1024;
constexpr int MAT_BYTES  = BM * CHUNK * 2;         // 8192 (one bf16 matrix chunk)
constexpr int STAGE_BYTES = 4 * MAT_BYTES;         // Ah, Al, Bh, Bl = 32768
constexpr int SMEM_TOTAL = SM_STAGE + 2 * STAGE_BYTES;  // 66560

// ---------------------------------------------------------------------------
// Helpers
// ---------------------------------------------------------------------------
__device__ __forceinline__ uint32_t smem_u32(const void* p) {
    uint32_t a;
    asm("{ .reg .u64 t; cvta.to.shared.u64 t, %1; cvt.u32.u64 %0, t; }" : "=r"(a) : "l"(p));
    return a;
}

// Rows are 64B (32 bf16). Two rows share a 128B line; SW128-style XOR keeps
// both STS and ldmatrix conflict-free.
//   line = r>>1, unit16B = (r&1)*4 + byte/16, phys unit = unit ^ (line&7)
__device__ __forceinline__ uint32_t phys(uint32_t r, uint32_t byte) {
    uint32_t line = r >> 1;
    uint32_t u = ((r & 1u) << 2) + (byte >> 4);
    return (line << 7) + ((u ^ (line & 7u)) << 4) + (byte & 15u);
}

#define LDSM4(r, a)                                                             \
    asm volatile("ldmatrix.sync.aligned.m8n8.x4.shared.b16 {%0,%1,%2,%3}, [%4];"\
        : "=r"((r)[0]), "=r"((r)[1]), "=r"((r)[2]), "=r"((r)[3]) : "r"(a))

#define MMA_BF16(c, a, b0, b1)                                                  \
    asm volatile("mma.sync.aligned.m16n8k16.row.col.f32.bf16.bf16.f32 "         \
        "{%0,%1,%2,%3},{%4,%5,%6,%7},{%8,%9},{%0,%1,%2,%3};"                    \
        : "+f"((c)[0]), "+f"((c)[1]), "+f"((c)[2]), "+f"((c)[3])                \
        : "r"((a)[0]), "r"((a)[1]), "r"((a)[2]), "r"((a)[3]), "r"(b0), "r"(b1))

// ---------------------------------------------------------------------------
// Scratch
// ---------------------------------------------------------------------------
__device__ int g_count[NT];
__device__ int g_offset[NT];
__device__ int g_fill[NT];
__device__ int g_is64;
__device__ int g_perm[NTOK];

__device__ __forceinline__ int get_type(const int* __restrict__ w, int i) {
    int v = g_is64 ? w[2 * i] : w[i];
    return v & (NT - 1);
}

// ---------------------------------------------------------------------------
// 1) init: zero counters + detect i_type dtype (int64 high words all zero)
// ---------------------------------------------------------------------------
__global__ void init_kernel(const int* __restrict__ w) {
    __shared__ int sOr[256];
    int tid = threadIdx.x;
    int acc = 0;
    for (int i = tid; i < NTOK / 2; i += 256) acc |= w[2 * i + 1];
    sOr[tid] = acc;
    __syncthreads();
    for (int s = 128; s > 0; s >>= 1) {
        if (tid < s) sOr[tid] |= sOr[tid + s];
        __syncthreads();
    }
    if (tid == 0) g_is64 = (sOr[0] == 0) ? 1 : 0;
    if (tid < NT) { g_count[tid] = 0; g_fill[tid] = 0; }
}

// ---------------------------------------------------------------------------
// 2) histogram
// ---------------------------------------------------------------------------
__global__ void hist_kernel(const int* __restrict__ w) {
    __shared__ int h[NT];
    int tid = threadIdx.x;
    if (tid < NT) h[tid] = 0;
    __syncthreads();
    int i = blockIdx.x * blockDim.x + tid;
    if (i < NTOK) atomicAdd(&h[get_type(w, i)], 1);
    __syncthreads();
    if (tid < NT && h[tid] > 0) atomicAdd(&g_count[tid], h[tid]);
}

// ---------------------------------------------------------------------------
// 3) scatter (scan computed locally per block; block 0 publishes g_offset)
// ---------------------------------------------------------------------------
__global__ void scatter_kernel(const int* __restrict__ w) {
    __shared__ int h[NT];
    __shared__ int base[NT];
    __shared__ int offs[NT];
    int tid = threadIdx.x;
    if (tid < NT) h[tid] = 0;
    if (tid == 0) {
        int s = 0;
        for (int t = 0; t < NT; t++) { offs[t] = s; s += g_count[t]; }
        if (blockIdx.x == 0)
            for (int t = 0; t < NT; t++) g_offset[t] = offs[t];
    }
    __syncthreads();

    int i = blockIdx.x * blockDim.x + tid;
    int t = 0, local = 0;
    if (i < NTOK) { t = get_type(w, i); local = atomicAdd(&h[t], 1); }
    __syncthreads();
    if (tid < NT) base[tid] = (h[tid] > 0) ? atomicAdd(&g_fill[tid], h[tid]) : 0;
    __syncthreads();
    if (i < NTOK) g_perm[offs[t] + base[t] + local] = i;
}

// ---------------------------------------------------------------------------
// 4) grouped GEMM: C = A_gather @ W_t^T + b_t via bf16 mma.sync, 3-term split
//    A = Ah + Al (hi = truncated top 16 bits, lo = exact residual -> bf16_rn)
//    C ~= Ah Bh + Al Bh + Ah Bl   (error ~2^-16 relative)
// ---------------------------------------------------------------------------
__global__ void __launch_bounds__(THREADS, 1)
gemm_kernel(const float* __restrict__ input,
            const float* __restrict__ weight,
            const float* __restrict__ bias,
            float* __restrict__ out) {
    const int t   = blockIdx.z;
    const int cnt = g_count[t];
    const int m0  = blockIdx.y * BM;
    if (m0 >= cnt) return;
    const int off = g_offset[t];
    const int n0  = blockIdx.x * BN;

    extern __shared__ __align__(128) char smem[];
    const uint32_t sb = smem_u32(smem);
    int*   s_idx  = (int*)(smem + SM_IDX);
    float* s_bias = (float*)(smem + SM_BIAS);

    const int tid = threadIdx.x;
    const int wid = tid >> 5;
    const int lid = tid & 31;
    const int warpm = wid >> 1;           // 0..3 -> m32 slice
    const int warpn = wid & 1;            // 0..1 -> n64 slice

    if (tid < BM) {
        int m = m0 + tid;
        s_idx[tid]  = (m < cnt) ? g_perm[off + m] : -1;
        s_bias[tid] = bias[t * OUTF + n0 + tid];
    }
    __syncthreads();

    const float* wt = weight + (size_t)t * OUTF * INF;

    // loader: l = tid + 256*i (i<4): row = l>>3 (0..127), q = l&7 (float4 idx)
    const float* aptr[4];
    const float* bptr[4];
    uint32_t sofs[4];
    bool aval[4];
#pragma unroll
    for (int i = 0; i < 4; i++) {
        int l = tid + THREADS * i;
        int row = l >> 3, q = l & 7;
        sofs[i] = phys((uint32_t)row, (uint32_t)(q * 8));
        int r = s_idx[row];
        aval[i] = (r >= 0);
        aptr[i] = input + (size_t)(r >= 0 ? r : 0) * INF + q * 4;
        bptr[i] = wt + (size_t)(n0 + row) * INF + q * 4;
    }

    float cacc[2][8][4];
#pragma unroll
    for (int mi = 0; mi < 2; mi++)
#pragma unroll
        for (int ni = 0; ni < 8; ni++)
#pragma unroll
            for (int e = 0; e < 4; e++) cacc[mi][ni][e] = 0.f;

    float4 pa[4], pb[4];

    auto ldg = [&](int k0) {
#pragma unroll
        for (int i = 0; i < 4; i++) {
            pa[i] = aval[i] ? *(const float4*)(aptr[i] + k0)
                            : make_float4(0.f, 0.f, 0.f, 0.f);
            pb[i] = *(const float4*)(bptr[i] + k0);
        }
    };

    // split one float4 into (hi bf16x4 at addr_hi, lo bf16x4 at addr_hi + MAT_BYTES)
    auto conv_store = [&](uint32_t addr_hi, float4 v) {
        uint32_t u0 = __float_as_uint(v.x), u1 = __float_as_uint(v.y);
        uint32_t u2 = __float_as_uint(v.z), u3 = __float_as_uint(v.w);
        uint32_t h01, h23;
        asm("prmt.b32 %0, %1, %2, 0x7632;" : "=r"(h01) : "r"(u0), "r"(u1));
        asm("prmt.b32 %0, %1, %2, 0x7632;" : "=r"(h23) : "r"(u2), "r"(u3));
        float l0 = v.x - __uint_as_float(u0 & 0xFFFF0000u);
        float l1 = v.y - __uint_as_float(u1 & 0xFFFF0000u);
        float l2 = v.z - __uint_as_float(u2 & 0xFFFF0000u);
        float l3 = v.w - __uint_as_float(u3 & 0xFFFF0000u);
        uint32_t L01, L23;   // first cvt operand -> upper 16 bits
        asm("cvt.rn.bf16x2.f32 %0, %1, %2;" : "=r"(L01) : "f"(l1), "f"(l0));
        asm("cvt.rn.bf16x2.f32 %0, %1, %2;" : "=r"(L23) : "f"(l3), "f"(l2));
        asm volatile("st.shared.v2.b32 [%0], {%1,%2};" :: "r"(addr_hi), "r"(h01), "r"(h23) : "memory");
        asm volatile("st.shared.v2.b32 [%0], {%1,%2};" ::
            "r"(addr_hi + MAT_BYTES), "r"(L01), "r"(L23) : "memory");
    };

    auto sts = [&](int stage) {
        uint32_t base = sb + SM_STAGE + stage * STAGE_BYTES;
#pragma unroll
        for (int i = 0; i < 4; i++) {
            conv_store(base + sofs[i], pa[i]);                     // Ah / Al
            conv_store(base + 2 * MAT_BYTES + sofs[i], pb[i]);     // Bh / Bl
        }
    };

    // ldmatrix per-lane row/byte pieces (x4 tile = 16 rows x 16 cols bf16):
    //   lanes 0-7: rows 0-7 klo | 8-15: rows 8-15 klo | 16-23: rows 0-7 khi | 24-31: rows 8-15 khi
    const int sub = lid >> 3;
    const int lrow = (lid & 7) + ((sub & 1) << 3);
    const uint32_t lbyte_base = (uint32_t)((sub >> 1) << 4);

    auto compute = [&](int stage) {
        uint32_t base = sb + SM_STAGE + stage * STAGE_BYTES;
#pragma unroll
        for (int c = 0; c < 2; c++) {                 // two k16 steps per chunk
            uint32_t byte = (uint32_t)(c * 32) + lbyte_base;
            uint32_t ah[2][4], al_[2][4];
#pragma unroll
            for (int mi = 0; mi < 2; mi++) {
                uint32_t ad = base + phys((uint32_t)(warpm * 32 + mi * 16 + lrow), byte);
                LDSM4(ah[mi], ad);
                LDSM4(al_[mi], ad + MAT_BYTES);
            }
            uint32_t bh[4][4], bl[4][4];
#pragma unroll
            for (int nb = 0; nb < 4; nb++) {
                uint32_t bd = base + 2 * MAT_BYTES +
                              phys((uint32_t)(warpn * 64 + nb * 16 + lrow), byte);
                LDSM4(bh[nb], bd);
                LDSM4(bl[nb], bd + MAT_BYTES);
            }
#pragma unroll
            for (int mi = 0; mi < 2; mi++)
#pragma unroll
                for (int nb = 0; nb < 4; nb++)
#pragma unroll
                    for (int h = 0; h < 2; h++) {
                        int ni = nb * 2 + h;
                        MMA_BF16(cacc[mi][ni], ah[mi],  bh[nb][h], bh[nb][h + 2]);
                        MMA_BF16(cacc[mi][ni], al_[mi], bh[nb][h], bh[nb][h + 2]);
                        MMA_BF16(cacc[mi][ni], ah[mi],  bl[nb][h], bl[nb][h + 2]);
                    }
        }
    };

    // pipeline: 2 smem stages, register prefetch of next chunk over compute
    ldg(0);
    sts(0);
    __syncthreads();
    for (int kt = 0; kt < NCHUNK; kt++) {
        const int cur = kt & 1;
        if (kt + 1 < NCHUNK) ldg((kt + 1) * CHUNK);
        compute(cur);
        if (kt + 1 < NCHUNK) sts(cur ^ 1);
        __syncthreads();
    }

    // epilogue: C frag (lane g=lid>>2, t2=lid&3): c0,c1 -> (g, 2t..), c2,c3 -> (g+8, 2t..)
    const int g  = lid >> 2;
    const int t2 = lid & 3;
#pragma unroll
    for (int mi = 0; mi < 2; mi++) {
        int row0 = warpm * 32 + mi * 16 + g;
        int row1 = row0 + 8;
        int r0 = s_idx[row0];
        int r1 = s_idx[row1];
#pragma unroll
        for (int ni = 0; ni < 8; ni++) {
            int col = warpn * 64 + ni * 8 + t2 * 2;
            float b0 = s_bias[col], b1 = s_bias[col + 1];
            if (r0 >= 0) {
                float2 o = make_float2(cacc[mi][ni][0] + b0, cacc[mi][ni][1] + b1);
                *(float2*)&out[(size_t)r0 * OUTF + n0 + col] = o;
            }
            if (r1 >= 0) {
                float2 o = make_float2(cacc[mi][ni][2] + b0, cacc[mi][ni][3] + b1);
                *(float2*)&out[(size_t)r1 * OUTF + n0 + col] = o;
            }
        }
    }
}

// ---------------------------------------------------------------------------
// launch
// ---------------------------------------------------------------------------
extern "C" void kernel_launch(void* const* d_in, const int* in_sizes, int n_in,
                              void* d_out, int out_size) {
    const float* input  = (const float*)d_in[0];
    const int*   itype  = (const int*)d_in[1];
    const float* weight = (const float*)d_in[2];
    const float* bias   = (const float*)d_in[3];
    float*       out    = (float*)d_out;

    cudaFuncSetAttribute(gemm_kernel,
                         cudaFuncAttributeMaxDynamicSharedMemorySize, SMEM_TOTAL);

    init_kernel<<<1, 256>>>(itype);
    hist_kernel<<<NTOK / 256, 256>>>(itype);
    scatter_kernel<<<NTOK / 256, 256>>>(itype);

    dim3 grid(OUTF / BN, MAX_MTILES, NT);
    gemm_kernel<<<grid, THREADS, SMEM_TOTAL>>>(input, weight, bias, out);
}